// round 9
// baseline (speedup 1.0000x reference)
#include <cuda_runtime.h>
#include <cuda_fp16.h>
#include <cstdint>

#define N_TOK 8192
#define HID   2048
#define NE    8

// ---------------------------------------------------------------------------
// Static device scratch
// ---------------------------------------------------------------------------
__device__ float  g_gate[N_TOK * NE];
__device__ __half g_xh [(size_t)N_TOK * HID];              // x in fp16
__device__ __half g_wth[(size_t)NE * HID * HID];           // W^T fp16 [e][f][h]

// ---------------------------------------------------------------------------
// PTX helpers (baseline sm_80/75-era only)
// ---------------------------------------------------------------------------
__device__ __forceinline__ uint32_t smem_u32(const void* p) {
    uint32_t a;
    asm("{ .reg .u64 t; cvta.to.shared.u64 t, %1; cvt.u32.u64 %0, t; }"
        : "=r"(a) : "l"(p));
    return a;
}
#define CP16(dst, src) \
    asm volatile("cp.async.cg.shared.global [%0], [%1], 16;" \
                 :: "r"(dst), "l"(src) : "memory")
#define CP_COMMIT() asm volatile("cp.async.commit_group;" ::: "memory")
#define CP_WAIT(n)  asm volatile("cp.async.wait_group %0;" :: "n"(n) : "memory")

#define LDSM_X4(r0, r1, r2, r3, a) \
    asm volatile("ldmatrix.sync.aligned.m8n8.x4.shared.b16 {%0,%1,%2,%3}, [%4];" \
                 : "=r"(r0), "=r"(r1), "=r"(r2), "=r"(r3) : "r"(a))

__device__ __forceinline__ void mma16816(float* d, const uint32_t* a,
                                         const uint32_t* bfr) {
    asm volatile(
        "mma.sync.aligned.m16n8k16.row.col.f32.f16.f16.f32 "
        "{%0,%1,%2,%3}, {%4,%5,%6,%7}, {%8,%9}, {%0,%1,%2,%3};"
        : "+f"(d[0]), "+f"(d[1]), "+f"(d[2]), "+f"(d[3])
        : "r"(a[0]), "r"(a[1]), "r"(a[2]), "r"(a[3]), "r"(bfr[0]), "r"(bfr[1]));
}

// ---------------------------------------------------------------------------
// Gate kernel (one warp per token): softmax(x @ Wg + bg) + x -> fp16 store
// ---------------------------------------------------------------------------
__global__ __launch_bounds__(256) void gate_kernel(const float* __restrict__ x,
                                                   const float* __restrict__ Wg,
                                                   const float* __restrict__ bg) {
    int warp = (blockIdx.x * blockDim.x + threadIdx.x) >> 5;
    int lane = threadIdx.x & 31;
    if (warp >= N_TOK) return;
    const float* xr = x + (size_t)warp * HID;
    float acc[NE];
#pragma unroll
    for (int e = 0; e < NE; e++) acc[e] = 0.f;
    for (int k0 = lane * 4; k0 < HID; k0 += 128) {
        float4 xv = *(const float4*)(xr + k0);
        // fused x -> fp16 conversion (same read)
        __align__(8) __half hx[4] = {
            __float2half_rn(xv.x), __float2half_rn(xv.y),
            __float2half_rn(xv.z), __float2half_rn(xv.w) };
        *(uint2*)&g_xh[(size_t)warp * HID + k0] = *(uint2*)hx;

        float xs[4] = {xv.x, xv.y, xv.z, xv.w};
        const float* wr = Wg + (size_t)k0 * NE;
#pragma unroll
        for (int r = 0; r < 4; r++) {
            float4 w0 = *(const float4*)(wr + r * NE);
            float4 w1 = *(const float4*)(wr + r * NE + 4);
            acc[0] += xs[r] * w0.x;  acc[1] += xs[r] * w0.y;
            acc[2] += xs[r] * w0.z;  acc[3] += xs[r] * w0.w;
            acc[4] += xs[r] * w1.x;  acc[5] += xs[r] * w1.y;
            acc[6] += xs[r] * w1.z;  acc[7] += xs[r] * w1.w;
        }
    }
#pragma unroll
    for (int e = 0; e < NE; e++)
#pragma unroll
        for (int o = 16; o; o >>= 1)
            acc[e] += __shfl_xor_sync(0xFFFFFFFFu, acc[e], o);
    if (lane == 0) {
#pragma unroll
        for (int e = 0; e < NE; e++) acc[e] += bg[e];
        float m = acc[0];
#pragma unroll
        for (int e = 1; e < NE; e++) m = fmaxf(m, acc[e]);
        float s = 0.f, p[NE];
#pragma unroll
        for (int e = 0; e < NE; e++) { p[e] = __expf(acc[e] - m); s += p[e]; }
        float inv = 1.f / s;
        float* gp = &g_gate[(size_t)warp * NE];
        *(float4*)(gp)     = make_float4(p[0]*inv, p[1]*inv, p[2]*inv, p[3]*inv);
        *(float4*)(gp + 4) = make_float4(p[4]*inv, p[5]*inv, p[6]*inv, p[7]*inv);
    }
}

// ---------------------------------------------------------------------------
// Transpose + convert W: W[e,h,f] fp32 -> Wt[e,f,h] fp16
// ---------------------------------------------------------------------------
__global__ __launch_bounds__(256) void transpose_w(const float* __restrict__ W) {
    __shared__ float tile[32][33];
    const int e  = blockIdx.z;
    const int h0 = blockIdx.y * 32;
    const int f0 = blockIdx.x * 32;
    const int tx = threadIdx.x & 31;
    const int ty = threadIdx.x >> 5;
#pragma unroll
    for (int i = 0; i < 32; i += 8)
        tile[ty + i][tx] = W[((size_t)e * HID + h0 + ty + i) * HID + f0 + tx];
    __syncthreads();
#pragma unroll
    for (int i = 0; i < 32; i += 8) {
        float v = tile[tx][ty + i];
        g_wth[((size_t)e * HID + f0 + ty + i) * HID + h0 + tx] = __float2half_rn(v);
    }
}

// ---------------------------------------------------------------------------
// Main mma.sync kernel (fp16 single-pass).
// CTA: 128 threads, tile 128x64. 4 warps (2x2), warp tile 64x32, BK=32.
// 4 CTAs/SM (independent barriers/pipelines interleave on the tensor pipe).
// NSLOT=3 ring, single barrier per stage, fragment-level software pipeline.
// 80B row stride => conflict-free ldmatrix. Expert-major loop (no modulo).
// ---------------------------------------------------------------------------
#define BK 32
#define ROWB 80                         // padded row stride for 64B of data
#define A_TILE_B (128 * ROWB)           // 10240
#define B_TILE_B (64 * ROWB)            // 5120
#define STAGE_B (A_TILE_B + B_TILE_B)   // 15360
#define NSLOT 3
#define SMEM_MAIN (NSLOT * STAGE_B)     // 46080
#define KCH (HID / BK)                  // 64 k-chunks per expert

__global__ __launch_bounds__(128, 4)
void moe_mma_kernel(const float* __restrict__ bias,
                    const float* __restrict__ cached,
                    float* __restrict__ out) {
    extern __shared__ char sm[];
    const uint32_t sbase = smem_u32(sm);

    const int tid  = threadIdx.x;
    const int wid  = tid >> 5;
    const int lane = tid & 31;
    const int n0 = blockIdx.y * 128;
    const int f0 = blockIdx.x * 64;
    const int warp_m = wid >> 1;        // 0..1
    const int warp_n = wid & 1;         // 0..1

    // ---- global->smem load mapping
    // A: 128 rows x 64B. thread t -> row t, 4 CP16
    const __half* srcA = g_xh + (size_t)(n0 + tid) * HID;
    const uint32_t dstA = (uint32_t)tid * ROWB;
    // B: 64 rows x 64B. thread t -> row t>>1, 32B chunk (t&1), 2 CP16
    const int br = tid >> 1;
    const int bc = (tid & 1) * 32;
    const size_t  bRow = (size_t)(f0 + br) * HID + (bc >> 1);
    const uint32_t dstB = A_TILE_B + (uint32_t)br * ROWB + bc;

    // ---- ldmatrix offsets
    const uint32_t offA = (uint32_t)(warp_m * 64 + (lane & 15)) * ROWB
                        + (uint32_t)(lane >> 4) * 16;
    const int matb = lane >> 3;
    const uint32_t offB = A_TILE_B
                        + (uint32_t)(warp_n * 32 + ((matb >> 1) * 8) + (lane & 7)) * ROWB
                        + (uint32_t)(matb & 1) * 16;

    float acc[4][4][4];
#pragma unroll
    for (int i = 0; i < 4; i++)
#pragma unroll
        for (int j = 0; j < 4; j++)
#pragma unroll
            for (int q = 0; q < 4; q++) acc[i][j][q] = 0.f;

    // slot base addresses (no modulo in hot loop)
    const uint32_t slotAddr[NSLOT] = { sbase, sbase + STAGE_B, sbase + 2 * STAGE_B };

    // loader: (expert e, k-chunk kt) -> slot
    auto load_stage = [&](int e, int kt, uint32_t slot) {
        const int k0 = kt * BK;
        const __half* pa = srcA + k0;
        const __half* pb = g_wth + (size_t)e * HID * HID + bRow + k0;
        const uint32_t da = slot + dstA;
        const uint32_t db = slot + dstB;
        CP16(da,      pa);       CP16(da + 16, pa + 8);
        CP16(da + 32, pa + 16);  CP16(da + 48, pa + 24);
        CP16(db,      pb);       CP16(db + 16, pb + 8);
        CP_COMMIT();
    };

    int wslot = 0;                      // next slot to write
    load_stage(0, 0, slotAddr[0]);
    load_stage(0, 1, slotAddr[1]);
    wslot = 2;
    int rslot = 0;                      // slot holding current stage

    for (int e = 0; e < NE; e++) {
        for (int kt = 0; kt < KCH; kt++) {
            const int gs = e * KCH + kt;           // global stage id
            const bool last = (gs == NE * KCH - 1);
            if (!last) CP_WAIT(1); else CP_WAIT(0);
            __syncthreads();
            // prefetch stage gs+2 into wslot (drained per the barrier above)
            if (gs + 2 < NE * KCH) {
                const int gn = gs + 2;
                load_stage(gn >> 6, gn & 63, slotAddr[wslot]);
                if (++wslot == NSLOT) wslot = 0;
            }

            const uint32_t stage = slotAddr[rslot];
            if (++rslot == NSLOT) rslot = 0;

            // ---- preload all B fragments (both ks)
            uint32_t bh[16];
            LDSM_X4(bh[0],  bh[1],  bh[2],  bh[3],  stage + offB);
            LDSM_X4(bh[4],  bh[5],  bh[6],  bh[7],  stage + offB + 16 * ROWB);
            LDSM_X4(bh[8],  bh[9],  bh[10], bh[11], stage + offB + 32);
            LDSM_X4(bh[12], bh[13], bh[14], bh[15], stage + offB + 16 * ROWB + 32);

            // ---- A-fragment software pipeline across 8 (ks,mt) groups
            uint32_t ah[2][4];
            LDSM_X4(ah[0][0], ah[0][1], ah[0][2], ah[0][3], stage + offA);
#pragma unroll
            for (int g = 0; g < 8; g++) {
                const int ks = g >> 2;
                const int mt = g & 3;
                const int cur = g & 1;
                if (g < 7) {
                    const int gn1 = g + 1;
                    LDSM_X4(ah[cur ^ 1][0], ah[cur ^ 1][1],
                            ah[cur ^ 1][2], ah[cur ^ 1][3],
                            stage + offA + (gn1 & 3) * (16 * ROWB) + (gn1 >> 2) * 32);
                }
#pragma unroll
                for (int nt = 0; nt < 4; nt++)
                    mma16816(acc[mt][nt], ah[cur], &bh[8 * ks + 2 * nt]);
            }
        }

        // ---- epilogue for expert e ----
#pragma unroll
        for (int nt = 0; nt < 4; nt++) {
            const int col = f0 + warp_n * 32 + nt * 8 + (lane & 3) * 2;
            const float2 bb = *(const float2*)&bias[(size_t)e * HID + col];
            const float2 cc = *(const float2*)&cached[(size_t)e * HID + col];
#pragma unroll
            for (int mt = 0; mt < 4; mt++) {
                const int row0 = n0 + warp_m * 64 + mt * 16 + (lane >> 2);
                const float g0 = g_gate[(size_t)row0 * NE + e];
                const float g1 = g_gate[(size_t)(row0 + 8) * NE + e];
                float* p0 = out + (size_t)row0 * HID + col;
                float* p1 = out + (size_t)(row0 + 8) * HID + col;
                float2 v0, v1;
                v0.x = g0 * (fmaxf(acc[mt][nt][0] + bb.x, 0.f) + cc.x);
                v0.y = g0 * (fmaxf(acc[mt][nt][1] + bb.y, 0.f) + cc.y);
                v1.x = g1 * (fmaxf(acc[mt][nt][2] + bb.x, 0.f) + cc.x);
                v1.y = g1 * (fmaxf(acc[mt][nt][3] + bb.y, 0.f) + cc.y);
                if (e == 0) {
                    *(float2*)p0 = v0;
                    *(float2*)p1 = v1;
                } else {
                    float2 o0 = *(const float2*)p0;
                    float2 o1 = *(const float2*)p1;
                    o0.x += v0.x; o0.y += v0.y;
                    o1.x += v1.x; o1.y += v1.y;
                    *(float2*)p0 = o0;
                    *(float2*)p1 = o1;
                }
                acc[mt][nt][0] = 0.f; acc[mt][nt][1] = 0.f;
                acc[mt][nt][2] = 0.f; acc[mt][nt][3] = 0.f;
            }
        }
    }
}

// ---------------------------------------------------------------------------
// Launch
// inputs: x[8192*2048], W[8*2048*2048], b[8*2048], Wg[2048*8], bg[8], cached[8*2048]
// ---------------------------------------------------------------------------
extern "C" void kernel_launch(void* const* d_in, const int* in_sizes, int n_in,
                              void* d_out, int out_size) {
    const float* x      = (const float*)d_in[0];
    const float* W      = (const float*)d_in[1];
    const float* b      = (const float*)d_in[2];
    const float* Wg     = (const float*)d_in[3];
    const float* bg     = (const float*)d_in[4];
    const float* cached = (const float*)d_in[5];
    float* out = (float*)d_out;

    gate_kernel<<<N_TOK / 8, 256>>>(x, Wg, bg);
    transpose_w<<<dim3(HID / 32, HID / 32, NE), 256>>>(W);

    static bool attr_set = false;
    if (!attr_set) {
        cudaFuncSetAttribute(moe_mma_kernel,
                             cudaFuncAttributeMaxDynamicSharedMemorySize, SMEM_MAIN);
        attr_set = true;
    }
    moe_mma_kernel<<<dim3(HID / 64, N_TOK / 128), 128, SMEM_MAIN>>>(b, cached, out);
}

// round 10
// speedup vs baseline: 1.1588x; 1.1588x over previous
#include <cuda_runtime.h>
#include <cuda_fp16.h>
#include <cstdint>

#define N_TOK 8192
#define HID   2048
#define NE    8

// ---------------------------------------------------------------------------
// Static device scratch
// ---------------------------------------------------------------------------
__device__ float  g_gate[N_TOK * NE];
__device__ __half g_xh [(size_t)N_TOK * HID];              // x in fp16
__device__ __half g_wth[(size_t)NE * HID * HID];           // W^T fp16 [e][f][h]

// ---------------------------------------------------------------------------
// PTX helpers (baseline sm_80/75-era only)
// ---------------------------------------------------------------------------
__device__ __forceinline__ uint32_t smem_u32(const void* p) {
    uint32_t a;
    asm("{ .reg .u64 t; cvta.to.shared.u64 t, %1; cvt.u32.u64 %0, t; }"
        : "=r"(a) : "l"(p));
    return a;
}
#define CP16(dst, src) \
    asm volatile("cp.async.cg.shared.global [%0], [%1], 16;" \
                 :: "r"(dst), "l"(src) : "memory")
#define CP_COMMIT() asm volatile("cp.async.commit_group;" ::: "memory")
#define CP_WAIT(n)  asm volatile("cp.async.wait_group %0;" :: "n"(n) : "memory")

#define LDSM_X4(r0, r1, r2, r3, a) \
    asm volatile("ldmatrix.sync.aligned.m8n8.x4.shared.b16 {%0,%1,%2,%3}, [%4];" \
                 : "=r"(r0), "=r"(r1), "=r"(r2), "=r"(r3) : "r"(a))

// fp16-accumulate MMA: D,C are 2 regs (4 halfs)
__device__ __forceinline__ void mma16816_f16(uint32_t* d, const uint32_t* a,
                                             const uint32_t* b) {
    asm volatile(
        "mma.sync.aligned.m16n8k16.row.col.f16.f16.f16.f16 "
        "{%0,%1}, {%2,%3,%4,%5}, {%6,%7}, {%0,%1};"
        : "+r"(d[0]), "+r"(d[1])
        : "r"(a[0]), "r"(a[1]), "r"(a[2]), "r"(a[3]), "r"(b[0]), "r"(b[1]));
}

// ---------------------------------------------------------------------------
// Gate kernel (one warp per token): softmax(x @ Wg + bg)  (fp32, exact)
// ---------------------------------------------------------------------------
__global__ __launch_bounds__(256) void gate_kernel(const float* __restrict__ x,
                                                   const float* __restrict__ Wg,
                                                   const float* __restrict__ bg) {
    int warp = (blockIdx.x * blockDim.x + threadIdx.x) >> 5;
    int lane = threadIdx.x & 31;
    if (warp >= N_TOK) return;
    const float* xr = x + (size_t)warp * HID;
    float acc[NE];
#pragma unroll
    for (int e = 0; e < NE; e++) acc[e] = 0.f;
#pragma unroll 4
    for (int k0 = lane * 4; k0 < HID; k0 += 128) {
        float4 xv = *(const float4*)(xr + k0);
        float xs[4] = {xv.x, xv.y, xv.z, xv.w};
        const float* wr = Wg + (size_t)k0 * NE;
#pragma unroll
        for (int r = 0; r < 4; r++) {
            float4 w0 = *(const float4*)(wr + r * NE);
            float4 w1 = *(const float4*)(wr + r * NE + 4);
            acc[0] += xs[r] * w0.x;  acc[1] += xs[r] * w0.y;
            acc[2] += xs[r] * w0.z;  acc[3] += xs[r] * w0.w;
            acc[4] += xs[r] * w1.x;  acc[5] += xs[r] * w1.y;
            acc[6] += xs[r] * w1.z;  acc[7] += xs[r] * w1.w;
        }
    }
#pragma unroll
    for (int e = 0; e < NE; e++)
#pragma unroll
        for (int o = 16; o; o >>= 1)
            acc[e] += __shfl_xor_sync(0xFFFFFFFFu, acc[e], o);
    if (lane == 0) {
#pragma unroll
        for (int e = 0; e < NE; e++) acc[e] += bg[e];
        float m = acc[0];
#pragma unroll
        for (int e = 1; e < NE; e++) m = fmaxf(m, acc[e]);
        float s = 0.f, p[NE];
#pragma unroll
        for (int e = 0; e < NE; e++) { p[e] = __expf(acc[e] - m); s += p[e]; }
        float inv = 1.f / s;
        float* gp = &g_gate[(size_t)warp * NE];
        *(float4*)(gp)     = make_float4(p[0]*inv, p[1]*inv, p[2]*inv, p[3]*inv);
        *(float4*)(gp + 4) = make_float4(p[4]*inv, p[5]*inv, p[6]*inv, p[7]*inv);
    }
}

// ---------------------------------------------------------------------------
// Convert x -> fp16
// ---------------------------------------------------------------------------
__global__ __launch_bounds__(256) void conv_x_kernel(const float* __restrict__ x) {
    size_t i = ((size_t)blockIdx.x * blockDim.x + threadIdx.x) * 8;
    float4 a = *(const float4*)(x + i);
    float4 c = *(const float4*)(x + i + 4);
    float v[8] = {a.x, a.y, a.z, a.w, c.x, c.y, c.z, c.w};
    __align__(16) __half h[8];
#pragma unroll
    for (int j = 0; j < 8; j++) h[j] = __float2half_rn(v[j]);
    *(uint4*)&g_xh[i] = *(uint4*)h;
}

// ---------------------------------------------------------------------------
// Transpose + convert W: W[e,h,f] fp32 -> Wt[e,f,h] fp16
// ---------------------------------------------------------------------------
__global__ __launch_bounds__(256) void transpose_w(const float* __restrict__ W) {
    __shared__ float tile[32][33];
    const int e  = blockIdx.z;
    const int h0 = blockIdx.y * 32;
    const int f0 = blockIdx.x * 32;
    const int tx = threadIdx.x & 31;
    const int ty = threadIdx.x >> 5;
#pragma unroll
    for (int i = 0; i < 32; i += 8)
        tile[ty + i][tx] = W[((size_t)e * HID + h0 + ty + i) * HID + f0 + tx];
    __syncthreads();
#pragma unroll
    for (int i = 0; i < 32; i += 8) {
        float v = tile[tx][ty + i];
        g_wth[((size_t)e * HID + f0 + ty + i) * HID + h0 + tx] = __float2half_rn(v);
    }
}

// ---------------------------------------------------------------------------
// Main mma.sync kernel: fp16 inputs, fp16 MMA accumulate, fp32 promote
// every 4 stages (k=128). CTA: 128x128, 8 warps (2x4), warp tile 64x32,
// BK=32, NSLOT=3 ring, single barrier/stage, frag pipelining.
// 80B row stride => conflict-free ldmatrix. 2 CTAs/SM target.
// ---------------------------------------------------------------------------
#define BK 32
#define ROWB 80
#define TILE_B (128 * ROWB)             // 10240
#define STAGE_B (2 * TILE_B)            // 20480
#define NSLOT 3
#define SMEM_MAIN (NSLOT * STAGE_B)     // 61440
#define TOT_ITERS (NE * (HID / BK))     // 512

__global__ __launch_bounds__(256, 2)
void moe_mma_kernel(const float* __restrict__ bias,
                    const float* __restrict__ cached,
                    float* __restrict__ out) {
    extern __shared__ char sm[];
    const uint32_t sbase = smem_u32(sm);

    const int tid  = threadIdx.x;
    const int wid  = tid >> 5;
    const int lane = tid & 31;
    const int n0 = blockIdx.y * 128;
    const int f0 = blockIdx.x * 128;
    const int warp_m = wid >> 2;
    const int warp_n = wid & 3;

    // ---- global->smem load mapping: thread t -> row t>>1, 32B chunk (t&1)
    const int lr = tid >> 1;
    const int lc = (tid & 1) * 32;
    const __half* srcA = g_xh + (size_t)(n0 + lr) * HID + (lc >> 1);
    const size_t  bRow = (size_t)(f0 + lr) * HID + (lc >> 1);
    const uint32_t dstOff = (uint32_t)lr * ROWB + lc;

    // ---- ldmatrix offsets
    const uint32_t offA = (uint32_t)(warp_m * 64 + (lane & 15)) * ROWB
                        + (uint32_t)(lane >> 4) * 16;
    const int matb = lane >> 3;
    const uint32_t offB = (uint32_t)(warp_n * 32 + ((matb >> 1) * 8) + (lane & 7)) * ROWB
                        + (uint32_t)(matb & 1) * 16;

    float    acc[4][4][4];     // fp32 master accumulators
    uint32_t a16[4][4][2];     // fp16 segment accumulators (4 halfs per tile)
#pragma unroll
    for (int i = 0; i < 4; i++)
#pragma unroll
        for (int j = 0; j < 4; j++) {
#pragma unroll
            for (int q = 0; q < 4; q++) acc[i][j][q] = 0.f;
            a16[i][j][0] = 0u; a16[i][j][1] = 0u;
        }

    const uint32_t slotAddr[NSLOT] = { sbase, sbase + STAGE_B, sbase + 2 * STAGE_B };

    auto load_stage = [&](int s, uint32_t slot) {
        const int e  = s >> 6;
        const int k0 = (s & 63) * BK;
        const uint32_t st = slot + dstOff;
        const __half* pa = srcA + k0;
        const __half* pb = g_wth + (size_t)e * HID * HID + bRow + k0;
        CP16(st,               pa);  CP16(st + 16,          pa + 8);
        CP16(st + TILE_B,      pb);  CP16(st + TILE_B + 16, pb + 8);
        CP_COMMIT();
    };

    load_stage(0, slotAddr[0]);
    load_stage(1, slotAddr[1]);
    int wslot = 2, rslot = 0;

    for (int s = 0; s < TOT_ITERS; s++) {
        if (s + 1 < TOT_ITERS) { CP_WAIT(1); }
        else                   { CP_WAIT(0); }
        __syncthreads();
        if (s + 2 < TOT_ITERS) {
            load_stage(s + 2, slotAddr[wslot]);
            if (++wslot == NSLOT) wslot = 0;
        }
        const uint32_t stage = slotAddr[rslot];
        if (++rslot == NSLOT) rslot = 0;

        // ---- ks-major compute; bh kept at 8 live regs
#pragma unroll
        for (int ks = 0; ks < 2; ks++) {
            uint32_t bh[8];
            LDSM_X4(bh[0], bh[1], bh[2], bh[3],
                    stage + TILE_B + offB + ks * 32);
            LDSM_X4(bh[4], bh[5], bh[6], bh[7],
                    stage + TILE_B + offB + 16 * ROWB + ks * 32);
            uint32_t ah[2][4];
            LDSM_X4(ah[0][0], ah[0][1], ah[0][2], ah[0][3],
                    stage + offA + ks * 32);
#pragma unroll
            for (int mt = 0; mt < 4; mt++) {
                const int cur = mt & 1;
                if (mt < 3) {
                    LDSM_X4(ah[cur ^ 1][0], ah[cur ^ 1][1],
                            ah[cur ^ 1][2], ah[cur ^ 1][3],
                            stage + offA + (mt + 1) * (16 * ROWB) + ks * 32);
                }
#pragma unroll
                for (int nt = 0; nt < 4; nt++)
                    mma16816_f16(a16[mt][nt], ah[cur], &bh[2 * nt]);
            }
        }

        // ---- promote fp16 segment accumulators to fp32 every 4 stages (k=128)
        if ((s & 3) == 3) {
#pragma unroll
            for (int mt = 0; mt < 4; mt++)
#pragma unroll
                for (int nt = 0; nt < 4; nt++) {
                    float2 f01 = __half22float2(*(__half2*)&a16[mt][nt][0]);
                    float2 f23 = __half22float2(*(__half2*)&a16[mt][nt][1]);
                    acc[mt][nt][0] += f01.x;  acc[mt][nt][1] += f01.y;
                    acc[mt][nt][2] += f23.x;  acc[mt][nt][3] += f23.y;
                    a16[mt][nt][0] = 0u;      a16[mt][nt][1] = 0u;
                }
        }

        if ((s & 63) == 63) {
            const int e = s >> 6;
#pragma unroll
            for (int nt = 0; nt < 4; nt++) {
                const int col = f0 + warp_n * 32 + nt * 8 + (lane & 3) * 2;
                const float2 bb = *(const float2*)&bias[(size_t)e * HID + col];
                const float2 cc = *(const float2*)&cached[(size_t)e * HID + col];
#pragma unroll
                for (int mt = 0; mt < 4; mt++) {
                    const int row0 = n0 + warp_m * 64 + mt * 16 + (lane >> 2);
                    const float g0 = g_gate[(size_t)row0 * NE + e];
                    const float g1 = g_gate[(size_t)(row0 + 8) * NE + e];
                    float* p0 = out + (size_t)row0 * HID + col;
                    float* p1 = out + (size_t)(row0 + 8) * HID + col;
                    float2 v0, v1;
                    v0.x = g0 * (fmaxf(acc[mt][nt][0] + bb.x, 0.f) + cc.x);
                    v0.y = g0 * (fmaxf(acc[mt][nt][1] + bb.y, 0.f) + cc.y);
                    v1.x = g1 * (fmaxf(acc[mt][nt][2] + bb.x, 0.f) + cc.x);
                    v1.y = g1 * (fmaxf(acc[mt][nt][3] + bb.y, 0.f) + cc.y);
                    if (e == 0) {
                        *(float2*)p0 = v0;
                        *(float2*)p1 = v1;
                    } else {
                        float2 o0 = *(const float2*)p0;
                        float2 o1 = *(const float2*)p1;
                        o0.x += v0.x; o0.y += v0.y;
                        o1.x += v1.x; o1.y += v1.y;
                        *(float2*)p0 = o0;
                        *(float2*)p1 = o1;
                    }
                    acc[mt][nt][0] = 0.f; acc[mt][nt][1] = 0.f;
                    acc[mt][nt][2] = 0.f; acc[mt][nt][3] = 0.f;
                }
            }
        }
    }
}

// ---------------------------------------------------------------------------
// Launch
// inputs: x[8192*2048], W[8*2048*2048], b[8*2048], Wg[2048*8], bg[8], cached[8*2048]
// ---------------------------------------------------------------------------
extern "C" void kernel_launch(void* const* d_in, const int* in_sizes, int n_in,
                              void* d_out, int out_size) {
    const float* x      = (const float*)d_in[0];
    const float* W      = (const float*)d_in[1];
    const float* b      = (const float*)d_in[2];
    const float* Wg     = (const float*)d_in[3];
    const float* bg     = (const float*)d_in[4];
    const float* cached = (const float*)d_in[5];
    float* out = (float*)d_out;

    gate_kernel<<<N_TOK / 8, 256>>>(x, Wg, bg);
    conv_x_kernel<<<(N_TOK * HID) / (256 * 8), 256>>>(x);
    transpose_w<<<dim3(HID / 32, HID / 32, NE), 256>>>(W);

    static bool attr_set = false;
    if (!attr_set) {
        cudaFuncSetAttribute(moe_mma_kernel,
                             cudaFuncAttributeMaxDynamicSharedMemorySize, SMEM_MAIN);
        attr_set = true;
    }
    moe_mma_kernel<<<dim3(HID / 128, N_TOK / 128), 256, SMEM_MAIN>>>(b, cached, out);
}

// round 11
// speedup vs baseline: 1.2176x; 1.0507x over previous
#include <cuda_runtime.h>
#include <cuda_fp16.h>
#include <cstdint>

#define N_TOK 8192
#define HID   2048
#define NE    8

// ---------------------------------------------------------------------------
// Static device scratch
// ---------------------------------------------------------------------------
__device__ float  g_gate[N_TOK * NE];
__device__ __half g_xh [(size_t)N_TOK * HID];              // x in fp16
__device__ __half g_wth[(size_t)NE * HID * HID];           // W^T fp16 [e][f][h]

// ---------------------------------------------------------------------------
// PTX helpers (baseline sm_80/75-era only)
// ---------------------------------------------------------------------------
__device__ __forceinline__ uint32_t smem_u32(const void* p) {
    uint32_t a;
    asm("{ .reg .u64 t; cvta.to.shared.u64 t, %1; cvt.u32.u64 %0, t; }"
        : "=r"(a) : "l"(p));
    return a;
}
#define CP16(dst, src) \
    asm volatile("cp.async.cg.shared.global [%0], [%1], 16;" \
                 :: "r"(dst), "l"(src) : "memory")
#define CP_COMMIT() asm volatile("cp.async.commit_group;" ::: "memory")
#define CP_WAIT(n)  asm volatile("cp.async.wait_group %0;" :: "n"(n) : "memory")

#define LDSM_X4(r0, r1, r2, r3, a) \
    asm volatile("ldmatrix.sync.aligned.m8n8.x4.shared.b16 {%0,%1,%2,%3}, [%4];" \
                 : "=r"(r0), "=r"(r1), "=r"(r2), "=r"(r3) : "r"(a))

__device__ __forceinline__ void mma16816(float* d, const uint32_t* a,
                                         const uint32_t* bfr) {
    asm volatile(
        "mma.sync.aligned.m16n8k16.row.col.f32.f16.f16.f32 "
        "{%0,%1,%2,%3}, {%4,%5,%6,%7}, {%8,%9}, {%0,%1,%2,%3};"
        : "+f"(d[0]), "+f"(d[1]), "+f"(d[2]), "+f"(d[3])
        : "r"(a[0]), "r"(a[1]), "r"(a[2]), "r"(a[3]), "r"(bfr[0]), "r"(bfr[1]));
}

// ---------------------------------------------------------------------------
// Gate kernel (one warp per token): softmax(x @ Wg + bg)  (fp32, exact)
// ---------------------------------------------------------------------------
__global__ __launch_bounds__(256) void gate_kernel(const float* __restrict__ x,
                                                   const float* __restrict__ Wg,
                                                   const float* __restrict__ bg) {
    int warp = (blockIdx.x * blockDim.x + threadIdx.x) >> 5;
    int lane = threadIdx.x & 31;
    if (warp >= N_TOK) return;
    const float* xr = x + (size_t)warp * HID;
    float acc[NE];
#pragma unroll
    for (int e = 0; e < NE; e++) acc[e] = 0.f;
    for (int k0 = lane * 4; k0 < HID; k0 += 128) {
        float4 xv = *(const float4*)(xr + k0);
        float xs[4] = {xv.x, xv.y, xv.z, xv.w};
        const float* wr = Wg + (size_t)k0 * NE;
#pragma unroll
        for (int r = 0; r < 4; r++) {
            float4 w0 = *(const float4*)(wr + r * NE);
            float4 w1 = *(const float4*)(wr + r * NE + 4);
            acc[0] += xs[r] * w0.x;  acc[1] += xs[r] * w0.y;
            acc[2] += xs[r] * w0.z;  acc[3] += xs[r] * w0.w;
            acc[4] += xs[r] * w1.x;  acc[5] += xs[r] * w1.y;
            acc[6] += xs[r] * w1.z;  acc[7] += xs[r] * w1.w;
        }
    }
#pragma unroll
    for (int e = 0; e < NE; e++)
#pragma unroll
        for (int o = 16; o; o >>= 1)
            acc[e] += __shfl_xor_sync(0xFFFFFFFFu, acc[e], o);
    if (lane == 0) {
#pragma unroll
        for (int e = 0; e < NE; e++) acc[e] += bg[e];
        float m = acc[0];
#pragma unroll
        for (int e = 1; e < NE; e++) m = fmaxf(m, acc[e]);
        float s = 0.f, p[NE];
#pragma unroll
        for (int e = 0; e < NE; e++) { p[e] = __expf(acc[e] - m); s += p[e]; }
        float inv = 1.f / s;
        float* gp = &g_gate[(size_t)warp * NE];
        *(float4*)(gp)     = make_float4(p[0]*inv, p[1]*inv, p[2]*inv, p[3]*inv);
        *(float4*)(gp + 4) = make_float4(p[4]*inv, p[5]*inv, p[6]*inv, p[7]*inv);
    }
}

// ---------------------------------------------------------------------------
// Convert x -> fp16
// ---------------------------------------------------------------------------
__global__ __launch_bounds__(256) void conv_x_kernel(const float* __restrict__ x) {
    size_t i = ((size_t)blockIdx.x * blockDim.x + threadIdx.x) * 8;
    float4 a = *(const float4*)(x + i);
    float4 c = *(const float4*)(x + i + 4);
    float v[8] = {a.x, a.y, a.z, a.w, c.x, c.y, c.z, c.w};
    __align__(16) __half h[8];
#pragma unroll
    for (int j = 0; j < 8; j++) h[j] = __float2half_rn(v[j]);
    *(uint4*)&g_xh[i] = *(uint4*)h;
}

// ---------------------------------------------------------------------------
// Transpose + convert W: W[e,h,f] fp32 -> Wt[e,f,h] fp16
// ---------------------------------------------------------------------------
__global__ __launch_bounds__(256) void transpose_w(const float* __restrict__ W) {
    __shared__ float tile[32][33];
    const int e  = blockIdx.z;
    const int h0 = blockIdx.y * 32;
    const int f0 = blockIdx.x * 32;
    const int tx = threadIdx.x & 31;
    const int ty = threadIdx.x >> 5;
#pragma unroll
    for (int i = 0; i < 32; i += 8)
        tile[ty + i][tx] = W[((size_t)e * HID + h0 + ty + i) * HID + f0 + tx];
    __syncthreads();
#pragma unroll
    for (int i = 0; i < 32; i += 8) {
        float v = tile[tx][ty + i];
        g_wth[((size_t)e * HID + f0 + ty + i) * HID + h0 + tx] = __float2half_rn(v);
    }
}

// ---------------------------------------------------------------------------
// Main mma.sync kernel (fp16 in, fp32 accumulate).
// CTA: 256 threads, tile 64x128. 8 warps (2x4), warp tile 32x32 (16 acc regs
// -> ~62 regs total -> 4 CTAs/SM = 32 warps/SM of TLP). BK=32, NSLOT=3 ring,
// single barrier/stage. 80B row stride => conflict-free ldmatrix.
// ---------------------------------------------------------------------------
#define BK 32
#define ROWB 80
#define A_TILE_B (64 * ROWB)            // 5120  (64 rows of A)
#define B_TILE_B (128 * ROWB)           // 10240 (128 cols of B)
#define STAGE_B (A_TILE_B + B_TILE_B)   // 15360
#define NSLOT 3
#define SMEM_MAIN (NSLOT * STAGE_B)     // 46080
#define TOT_ITERS (NE * (HID / BK))     // 512

__global__ __launch_bounds__(256, 4)
void moe_mma_kernel(const float* __restrict__ bias,
                    const float* __restrict__ cached,
                    float* __restrict__ out) {
    extern __shared__ char sm[];
    const uint32_t sbase = smem_u32(sm);

    const int tid  = threadIdx.x;
    const int wid  = tid >> 5;
    const int lane = tid & 31;
    const int n0 = blockIdx.y * 64;      // token rows
    const int f0 = blockIdx.x * 128;     // feature cols
    const int warp_m = wid >> 2;         // 0..1 (32 rows each)
    const int warp_n = wid & 3;          // 0..3 (32 cols each)

    // ---- global->smem load mapping
    // A: 64 rows x 64B -> 256 CP16, 1 per thread: row=t>>2, chunk=(t&3)*16
    const int arow = tid >> 2;
    const int acol = (tid & 3) * 16;
    const __half* srcA = g_xh + (size_t)(n0 + arow) * HID + (acol >> 1);
    const uint32_t dstA = (uint32_t)arow * ROWB + acol;
    // B: 128 rows x 64B -> 512 CP16, 2 per thread: row=t>>1, chunk=(t&1)*32
    const int brow = tid >> 1;
    const int bcol = (tid & 1) * 32;
    const size_t  bRow = (size_t)(f0 + brow) * HID + (bcol >> 1);
    const uint32_t dstB = A_TILE_B + (uint32_t)brow * ROWB + bcol;

    // ---- ldmatrix offsets
    const uint32_t offA = (uint32_t)(warp_m * 32 + (lane & 15)) * ROWB
                        + (uint32_t)(lane >> 4) * 16;
    const int matb = lane >> 3;
    const uint32_t offB = A_TILE_B
                        + (uint32_t)(warp_n * 32 + ((matb >> 1) * 8) + (lane & 7)) * ROWB
                        + (uint32_t)(matb & 1) * 16;

    float acc[2][4][4];
#pragma unroll
    for (int i = 0; i < 2; i++)
#pragma unroll
        for (int j = 0; j < 4; j++)
#pragma unroll
            for (int q = 0; q < 4; q++) acc[i][j][q] = 0.f;

    const uint32_t slotAddr[NSLOT] = { sbase, sbase + STAGE_B, sbase + 2 * STAGE_B };

    auto load_stage = [&](int s, uint32_t slot) {
        const int e  = s >> 6;
        const int k0 = (s & 63) * BK;
        const __half* pa = srcA + k0;
        const __half* pb = g_wth + (size_t)e * HID * HID + bRow + k0;
        CP16(slot + dstA,      pa);
        CP16(slot + dstB,      pb);
        CP16(slot + dstB + 16, pb + 8);
        CP_COMMIT();
    };

    load_stage(0, slotAddr[0]);
    load_stage(1, slotAddr[1]);
    int wslot = 2, rslot = 0;

    for (int s = 0; s < TOT_ITERS; s++) {
        if (s + 1 < TOT_ITERS) { CP_WAIT(1); }
        else                   { CP_WAIT(0); }
        __syncthreads();
        if (s + 2 < TOT_ITERS) {
            load_stage(s + 2, slotAddr[wslot]);
            if (++wslot == NSLOT) wslot = 0;
        }
        const uint32_t stage = slotAddr[rslot];
        if (++rslot == NSLOT) rslot = 0;

#pragma unroll
        for (int ks = 0; ks < 2; ks++) {
            uint32_t bh[8];
            LDSM_X4(bh[0], bh[1], bh[2], bh[3],
                    stage + offB + ks * 32);
            LDSM_X4(bh[4], bh[5], bh[6], bh[7],
                    stage + offB + 16 * ROWB + ks * 32);
#pragma unroll
            for (int mt = 0; mt < 2; mt++) {
                uint32_t ah[4];
                LDSM_X4(ah[0], ah[1], ah[2], ah[3],
                        stage + offA + mt * (16 * ROWB) + ks * 32);
#pragma unroll
                for (int nt = 0; nt < 4; nt++)
                    mma16816(acc[mt][nt], ah, &bh[2 * nt]);
            }
        }

        if ((s & 63) == 63) {
            const int e = s >> 6;
#pragma unroll
            for (int nt = 0; nt < 4; nt++) {
                const int col = f0 + warp_n * 32 + nt * 8 + (lane & 3) * 2;
                const float2 bb = *(const float2*)&bias[(size_t)e * HID + col];
                const float2 cc = *(const float2*)&cached[(size_t)e * HID + col];
#pragma unroll
                for (int mt = 0; mt < 2; mt++) {
                    const int row0 = n0 + warp_m * 32 + mt * 16 + (lane >> 2);
                    const float g0 = g_gate[(size_t)row0 * NE + e];
                    const float g1 = g_gate[(size_t)(row0 + 8) * NE + e];
                    float* p0 = out + (size_t)row0 * HID + col;
                    float* p1 = out + (size_t)(row0 + 8) * HID + col;
                    float2 v0, v1;
                    v0.x = g0 * (fmaxf(acc[mt][nt][0] + bb.x, 0.f) + cc.x);
                    v0.y = g0 * (fmaxf(acc[mt][nt][1] + bb.y, 0.f) + cc.y);
                    v1.x = g1 * (fmaxf(acc[mt][nt][2] + bb.x, 0.f) + cc.x);
                    v1.y = g1 * (fmaxf(acc[mt][nt][3] + bb.y, 0.f) + cc.y);
                    if (e == 0) {
                        *(float2*)p0 = v0;
                        *(float2*)p1 = v1;
                    } else {
                        float2 o0 = *(const float2*)p0;
                        float2 o1 = *(const float2*)p1;
                        o0.x += v0.x; o0.y += v0.y;
                        o1.x += v1.x; o1.y += v1.y;
                        *(float2*)p0 = o0;
                        *(float2*)p1 = o1;
                    }
                    acc[mt][nt][0] = 0.f; acc[mt][nt][1] = 0.f;
                    acc[mt][nt][2] = 0.f; acc[mt][nt][3] = 0.f;
                }
            }
        }
    }
}

// ---------------------------------------------------------------------------
// Launch
// inputs: x[8192*2048], W[8*2048*2048], b[8*2048], Wg[2048*8], bg[8], cached[8*2048]
// ---------------------------------------------------------------------------
extern "C" void kernel_launch(void* const* d_in, const int* in_sizes, int n_in,
                              void* d_out, int out_size) {
    const float* x      = (const float*)d_in[0];
    const float* W      = (const float*)d_in[1];
    const float* b      = (const float*)d_in[2];
    const float* Wg     = (const float*)d_in[3];
    const float* bg     = (const float*)d_in[4];
    const float* cached = (const float*)d_in[5];
    float* out = (float*)d_out;

    gate_kernel<<<N_TOK / 8, 256>>>(x, Wg, bg);
    conv_x_kernel<<<(N_TOK * HID) / (256 * 8), 256>>>(x);
    transpose_w<<<dim3(HID / 32, HID / 32, NE), 256>>>(W);

    static bool attr_set = false;
    if (!attr_set) {
        cudaFuncSetAttribute(moe_mma_kernel,
                             cudaFuncAttributeMaxDynamicSharedMemorySize, SMEM_MAIN);
        attr_set = true;
    }
    moe_mma_kernel<<<dim3(HID / 128, N_TOK / 64), 256, SMEM_MAIN>>>(b, cached, out);
}

// round 12
// speedup vs baseline: 1.2638x; 1.0380x over previous
#include <cuda_runtime.h>
#include <cuda_fp16.h>
#include <cstdint>

#define N_TOK 8192
#define HID   2048
#define NE    8

// ---------------------------------------------------------------------------
// Static device scratch
// ---------------------------------------------------------------------------
__device__ float  g_gate[N_TOK * NE];
__device__ __half g_xh [(size_t)N_TOK * HID];              // x in fp16
__device__ __half g_wth[(size_t)NE * HID * HID];           // W^T fp16 [e][f][h]

// ---------------------------------------------------------------------------
// PTX helpers (baseline sm_80/75-era only)
// ---------------------------------------------------------------------------
__device__ __forceinline__ uint32_t smem_u32(const void* p) {
    uint32_t a;
    asm("{ .reg .u64 t; cvta.to.shared.u64 t, %1; cvt.u32.u64 %0, t; }"
        : "=r"(a) : "l"(p));
    return a;
}
#define CP16(dst, src) \
    asm volatile("cp.async.cg.shared.global [%0], [%1], 16;" \
                 :: "r"(dst), "l"(src) : "memory")
#define CP_COMMIT() asm volatile("cp.async.commit_group;" ::: "memory")
#define CP_WAIT(n)  asm volatile("cp.async.wait_group %0;" :: "n"(n) : "memory")

#define LDSM_X4(r0, r1, r2, r3, a) \
    asm volatile("ldmatrix.sync.aligned.m8n8.x4.shared.b16 {%0,%1,%2,%3}, [%4];" \
                 : "=r"(r0), "=r"(r1), "=r"(r2), "=r"(r3) : "r"(a))

__device__ __forceinline__ void mma16816(float* d, const uint32_t* a,
                                         const uint32_t* bfr) {
    asm volatile(
        "mma.sync.aligned.m16n8k16.row.col.f32.f16.f16.f32 "
        "{%0,%1,%2,%3}, {%4,%5,%6,%7}, {%8,%9}, {%0,%1,%2,%3};"
        : "+f"(d[0]), "+f"(d[1]), "+f"(d[2]), "+f"(d[3])
        : "r"(a[0]), "r"(a[1]), "r"(a[2]), "r"(a[3]), "r"(bfr[0]), "r"(bfr[1]));
}

// ---------------------------------------------------------------------------
// Gate kernel (one warp per token): softmax(x @ Wg + bg)  (fp32, exact)
// ---------------------------------------------------------------------------
__global__ __launch_bounds__(256) void gate_kernel(const float* __restrict__ x,
                                                   const float* __restrict__ Wg,
                                                   const float* __restrict__ bg) {
    int warp = (blockIdx.x * blockDim.x + threadIdx.x) >> 5;
    int lane = threadIdx.x & 31;
    if (warp >= N_TOK) return;
    const float* xr = x + (size_t)warp * HID;
    float acc[NE];
#pragma unroll
    for (int e = 0; e < NE; e++) acc[e] = 0.f;
    for (int k0 = lane * 4; k0 < HID; k0 += 128) {
        float4 xv = *(const float4*)(xr + k0);
        float xs[4] = {xv.x, xv.y, xv.z, xv.w};
        const float* wr = Wg + (size_t)k0 * NE;
#pragma unroll
        for (int r = 0; r < 4; r++) {
            float4 w0 = *(const float4*)(wr + r * NE);
            float4 w1 = *(const float4*)(wr + r * NE + 4);
            acc[0] += xs[r] * w0.x;  acc[1] += xs[r] * w0.y;
            acc[2] += xs[r] * w0.z;  acc[3] += xs[r] * w0.w;
            acc[4] += xs[r] * w1.x;  acc[5] += xs[r] * w1.y;
            acc[6] += xs[r] * w1.z;  acc[7] += xs[r] * w1.w;
        }
    }
#pragma unroll
    for (int e = 0; e < NE; e++)
#pragma unroll
        for (int o = 16; o; o >>= 1)
            acc[e] += __shfl_xor_sync(0xFFFFFFFFu, acc[e], o);
    if (lane == 0) {
#pragma unroll
        for (int e = 0; e < NE; e++) acc[e] += bg[e];
        float m = acc[0];
#pragma unroll
        for (int e = 1; e < NE; e++) m = fmaxf(m, acc[e]);
        float s = 0.f, p[NE];
#pragma unroll
        for (int e = 0; e < NE; e++) { p[e] = __expf(acc[e] - m); s += p[e]; }
        float inv = 1.f / s;
        float* gp = &g_gate[(size_t)warp * NE];
        *(float4*)(gp)     = make_float4(p[0]*inv, p[1]*inv, p[2]*inv, p[3]*inv);
        *(float4*)(gp + 4) = make_float4(p[4]*inv, p[5]*inv, p[6]*inv, p[7]*inv);
    }
}

// ---------------------------------------------------------------------------
// Convert x -> fp16
// ---------------------------------------------------------------------------
__global__ __launch_bounds__(256) void conv_x_kernel(const float* __restrict__ x) {
    size_t i = ((size_t)blockIdx.x * blockDim.x + threadIdx.x) * 8;
    float4 a = *(const float4*)(x + i);
    float4 c = *(const float4*)(x + i + 4);
    float v[8] = {a.x, a.y, a.z, a.w, c.x, c.y, c.z, c.w};
    __align__(16) __half h[8];
#pragma unroll
    for (int j = 0; j < 8; j++) h[j] = __float2half_rn(v[j]);
    *(uint4*)&g_xh[i] = *(uint4*)h;
}

// ---------------------------------------------------------------------------
// Transpose + convert W: W[e,h,f] fp32 -> Wt[e,f,h] fp16
// ---------------------------------------------------------------------------
__global__ __launch_bounds__(256) void transpose_w(const float* __restrict__ W) {
    __shared__ float tile[32][33];
    const int e  = blockIdx.z;
    const int h0 = blockIdx.y * 32;
    const int f0 = blockIdx.x * 32;
    const int tx = threadIdx.x & 31;
    const int ty = threadIdx.x >> 5;
#pragma unroll
    for (int i = 0; i < 32; i += 8)
        tile[ty + i][tx] = W[((size_t)e * HID + h0 + ty + i) * HID + f0 + tx];
    __syncthreads();
#pragma unroll
    for (int i = 0; i < 32; i += 8) {
        float v = tile[tx][ty + i];
        g_wth[((size_t)e * HID + f0 + ty + i) * HID + h0 + tx] = __float2half_rn(v);
    }
}

// ---------------------------------------------------------------------------
// Main mma.sync kernel (fp16 in, fp32 accumulate).
// CTA: 512 threads, tile 256x128. 16 warps (4x4), warp tile 64x32, BK=32.
// 1 CTA/SM (RF-bound), NSLOT=4 ring with 3 stages in flight, single barrier
// per stage. LDGSTS:HMMA ratio 3 (vs 4 at 128x128) and B redundancy halved.
// 80B row stride => conflict-free ldmatrix.
// ---------------------------------------------------------------------------
#define BK 32
#define ROWB 80
#define A_TILE_B (256 * ROWB)           // 20480 (256 token rows)
#define B_TILE_B (128 * ROWB)           // 10240 (128 feature cols)
#define STAGE_B (A_TILE_B + B_TILE_B)   // 30720
#define NSLOT 4
#define SMEM_MAIN (NSLOT * STAGE_B)     // 122880
#define TOT_ITERS (NE * (HID / BK))     // 512

__global__ __launch_bounds__(512, 1)
void moe_mma_kernel(const float* __restrict__ bias,
                    const float* __restrict__ cached,
                    float* __restrict__ out) {
    extern __shared__ char sm[];
    const uint32_t sbase = smem_u32(sm);

    const int tid  = threadIdx.x;
    const int wid  = tid >> 5;
    const int lane = tid & 31;
    const int n0 = blockIdx.y * 256;     // token rows
    const int f0 = blockIdx.x * 128;     // feature cols
    const int warp_m = wid >> 2;         // 0..3 (64 rows each)
    const int warp_n = wid & 3;          // 0..3 (32 cols each)

    // ---- global->smem load mapping
    // A: 256 rows x 64B = 1024 CP16; thread t: row t>>1, 32B chunk (t&1)
    const int arow = tid >> 1;
    const int acol = (tid & 1) * 32;
    const __half* srcA = g_xh + (size_t)(n0 + arow) * HID + (acol >> 1);
    const uint32_t dstA = (uint32_t)arow * ROWB + acol;
    // B: 128 rows x 64B = 512 CP16; thread t: row t>>2, 16B chunk (t&3)
    const int brow = tid >> 2;
    const int bcol = (tid & 3) * 16;
    const size_t  bRow = (size_t)(f0 + brow) * HID + (bcol >> 1);
    const uint32_t dstB = A_TILE_B + (uint32_t)brow * ROWB + bcol;

    // ---- ldmatrix offsets
    const uint32_t offA = (uint32_t)(warp_m * 64 + (lane & 15)) * ROWB
                        + (uint32_t)(lane >> 4) * 16;
    const int matb = lane >> 3;
    const uint32_t offB = A_TILE_B
                        + (uint32_t)(warp_n * 32 + ((matb >> 1) * 8) + (lane & 7)) * ROWB
                        + (uint32_t)(matb & 1) * 16;

    float acc[4][4][4];
#pragma unroll
    for (int i = 0; i < 4; i++)
#pragma unroll
        for (int j = 0; j < 4; j++)
#pragma unroll
            for (int q = 0; q < 4; q++) acc[i][j][q] = 0.f;

    const uint32_t slotAddr[NSLOT] = { sbase, sbase + STAGE_B,
                                       sbase + 2 * STAGE_B, sbase + 3 * STAGE_B };

    auto load_stage = [&](int s, uint32_t slot) {
        const int e  = s >> 6;
        const int k0 = (s & 63) * BK;
        const __half* pa = srcA + k0;
        const __half* pb = g_wth + (size_t)e * HID * HID + bRow + k0;
        CP16(slot + dstA,      pa);
        CP16(slot + dstA + 16, pa + 8);
        CP16(slot + dstB,      pb);
        CP_COMMIT();
    };

    load_stage(0, slotAddr[0]);
    load_stage(1, slotAddr[1]);
    load_stage(2, slotAddr[2]);
    int wslot = 3, rslot = 0;

    for (int s = 0; s < TOT_ITERS; s++) {
        // complete stage s (pending groups: s..min(s+2, last))
        const int rem = TOT_ITERS - 1 - s;
        if      (rem >= 2) { CP_WAIT(2); }
        else if (rem == 1) { CP_WAIT(1); }
        else               { CP_WAIT(0); }
        __syncthreads();
        // slot (s+3)%4 == slot (s-1)%4 was drained by the barrier above
        if (s + 3 < TOT_ITERS) {
            load_stage(s + 3, slotAddr[wslot]);
            if (++wslot == NSLOT) wslot = 0;
        }
        const uint32_t stage = slotAddr[rslot];
        if (++rslot == NSLOT) rslot = 0;

        // ---- preload all B fragments for this stage (both ks)
        uint32_t bh[16];
#pragma unroll
        for (int ks = 0; ks < 2; ks++) {
            LDSM_X4(bh[8*ks+0], bh[8*ks+1], bh[8*ks+2], bh[8*ks+3],
                    stage + offB + ks * 32);
            LDSM_X4(bh[8*ks+4], bh[8*ks+5], bh[8*ks+6], bh[8*ks+7],
                    stage + offB + 16 * ROWB + ks * 32);
        }

        // ---- A-fragment software pipeline across 8 (ks,mt) groups
        uint32_t ah[2][4];
        LDSM_X4(ah[0][0], ah[0][1], ah[0][2], ah[0][3], stage + offA);
#pragma unroll
        for (int g = 0; g < 8; g++) {
            const int ks = g >> 2;
            const int mt = g & 3;
            const int cur = g & 1;
            if (g < 7) {
                const int gn = g + 1;
                LDSM_X4(ah[cur ^ 1][0], ah[cur ^ 1][1],
                        ah[cur ^ 1][2], ah[cur ^ 1][3],
                        stage + offA + (gn & 3) * (16 * ROWB) + (gn >> 2) * 32);
            }
#pragma unroll
            for (int nt = 0; nt < 4; nt++)
                mma16816(acc[mt][nt], ah[cur], &bh[8 * ks + 2 * nt]);
        }

        if ((s & 63) == 63) {
            const int e = s >> 6;
#pragma unroll
            for (int nt = 0; nt < 4; nt++) {
                const int col = f0 + warp_n * 32 + nt * 8 + (lane & 3) * 2;
                const float2 bb = *(const float2*)&bias[(size_t)e * HID + col];
                const float2 cc = *(const float2*)&cached[(size_t)e * HID + col];
#pragma unroll
                for (int mt = 0; mt < 4; mt++) {
                    const int row0 = n0 + warp_m * 64 + mt * 16 + (lane >> 2);
                    const float g0 = g_gate[(size_t)row0 * NE + e];
                    const float g1 = g_gate[(size_t)(row0 + 8) * NE + e];
                    float* p0 = out + (size_t)row0 * HID + col;
                    float* p1 = out + (size_t)(row0 + 8) * HID + col;
                    float2 v0, v1;
                    v0.x = g0 * (fmaxf(acc[mt][nt][0] + bb.x, 0.f) + cc.x);
                    v0.y = g0 * (fmaxf(acc[mt][nt][1] + bb.y, 0.f) + cc.y);
                    v1.x = g1 * (fmaxf(acc[mt][nt][2] + bb.x, 0.f) + cc.x);
                    v1.y = g1 * (fmaxf(acc[mt][nt][3] + bb.y, 0.f) + cc.y);
                    if (e == 0) {
                        *(float2*)p0 = v0;
                        *(float2*)p1 = v1;
                    } else {
                        float2 o0 = *(const float2*)p0;
                        float2 o1 = *(const float2*)p1;
                        o0.x += v0.x; o0.y += v0.y;
                        o1.x += v1.x; o1.y += v1.y;
                        *(float2*)p0 = o0;
                        *(float2*)p1 = o1;
                    }
                    acc[mt][nt][0] = 0.f; acc[mt][nt][1] = 0.f;
                    acc[mt][nt][2] = 0.f; acc[mt][nt][3] = 0.f;
                }
            }
        }
    }
}

// ---------------------------------------------------------------------------
// Launch
// inputs: x[8192*2048], W[8*2048*2048], b[8*2048], Wg[2048*8], bg[8], cached[8*2048]
// ---------------------------------------------------------------------------
extern "C" void kernel_launch(void* const* d_in, const int* in_sizes, int n_in,
                              void* d_out, int out_size) {
    const float* x      = (const float*)d_in[0];
    const float* W      = (const float*)d_in[1];
    const float* b      = (const float*)d_in[2];
    const float* Wg     = (const float*)d_in[3];
    const float* bg     = (const float*)d_in[4];
    const float* cached = (const float*)d_in[5];
    float* out = (float*)d_out;

    gate_kernel<<<N_TOK / 8, 256>>>(x, Wg, bg);
    conv_x_kernel<<<(N_TOK * HID) / (256 * 8), 256>>>(x);
    transpose_w<<<dim3(HID / 32, HID / 32, NE), 256>>>(W);

    static bool attr_set = false;
    if (!attr_set) {
        cudaFuncSetAttribute(moe_mma_kernel,
                             cudaFuncAttributeMaxDynamicSharedMemorySize, SMEM_MAIN);
        attr_set = true;
    }
    moe_mma_kernel<<<dim3(HID / 128, N_TOK / 256), 512, SMEM_MAIN>>>(b, cached, out);
}

// round 14
// speedup vs baseline: 1.3778x; 1.0902x over previous
#include <cuda_runtime.h>
#include <cuda_fp16.h>
#include <cstdint>

#define N_TOK 8192
#define HID   2048
#define NE    8

// ---------------------------------------------------------------------------
// Static device scratch
// ---------------------------------------------------------------------------
__device__ float  g_gate[N_TOK * NE];
__device__ __half g_xh [(size_t)N_TOK * HID];              // x in fp16
__device__ __half g_wth[(size_t)NE * HID * HID];           // W^T fp16 [e][f][h]

// ---------------------------------------------------------------------------
// PTX helpers (baseline sm_80/75-era only)
// ---------------------------------------------------------------------------
__device__ __forceinline__ uint32_t smem_u32(const void* p) {
    uint32_t a;
    asm("{ .reg .u64 t; cvta.to.shared.u64 t, %1; cvt.u32.u64 %0, t; }"
        : "=r"(a) : "l"(p));
    return a;
}
#define CP16(dst, src) \
    asm volatile("cp.async.cg.shared.global [%0], [%1], 16;" \
                 :: "r"(dst), "l"(src) : "memory")
#define CP_COMMIT() asm volatile("cp.async.commit_group;" ::: "memory")
#define CP_WAIT(n)  asm volatile("cp.async.wait_group %0;" :: "n"(n) : "memory")

#define LDSM_X4(r0, r1, r2, r3, a) \
    asm volatile("ldmatrix.sync.aligned.m8n8.x4.shared.b16 {%0,%1,%2,%3}, [%4];" \
                 : "=r"(r0), "=r"(r1), "=r"(r2), "=r"(r3) : "r"(a))

__device__ __forceinline__ void mma16816(float* d, const uint32_t* a,
                                         const uint32_t* bfr) {
    asm volatile(
        "mma.sync.aligned.m16n8k16.row.col.f32.f16.f16.f32 "
        "{%0,%1,%2,%3}, {%4,%5,%6,%7}, {%8,%9}, {%0,%1,%2,%3};"
        : "+f"(d[0]), "+f"(d[1]), "+f"(d[2]), "+f"(d[3])
        : "r"(a[0]), "r"(a[1]), "r"(a[2]), "r"(a[3]), "r"(bfr[0]), "r"(bfr[1]));
}

// ---------------------------------------------------------------------------
// Gate kernel (one warp per token): softmax(x @ Wg + bg)  (fp32, exact)
// ---------------------------------------------------------------------------
__global__ __launch_bounds__(256) void gate_kernel(const float* __restrict__ x,
                                                   const float* __restrict__ Wg,
                                                   const float* __restrict__ bg) {
    int warp = (blockIdx.x * blockDim.x + threadIdx.x) >> 5;
    int lane = threadIdx.x & 31;
    if (warp >= N_TOK) return;
    const float* xr = x + (size_t)warp * HID;
    float acc[NE];
#pragma unroll
    for (int e = 0; e < NE; e++) acc[e] = 0.f;
    for (int k0 = lane * 4; k0 < HID; k0 += 128) {
        float4 xv = *(const float4*)(xr + k0);
        float xs[4] = {xv.x, xv.y, xv.z, xv.w};
        const float* wr = Wg + (size_t)k0 * NE;
#pragma unroll
        for (int r = 0; r < 4; r++) {
            float4 w0 = *(const float4*)(wr + r * NE);
            float4 w1 = *(const float4*)(wr + r * NE + 4);
            acc[0] += xs[r] * w0.x;  acc[1] += xs[r] * w0.y;
            acc[2] += xs[r] * w0.z;  acc[3] += xs[r] * w0.w;
            acc[4] += xs[r] * w1.x;  acc[5] += xs[r] * w1.y;
            acc[6] += xs[r] * w1.z;  acc[7] += xs[r] * w1.w;
        }
    }
#pragma unroll
    for (int e = 0; e < NE; e++)
#pragma unroll
        for (int o = 16; o; o >>= 1)
            acc[e] += __shfl_xor_sync(0xFFFFFFFFu, acc[e], o);
    if (lane == 0) {
#pragma unroll
        for (int e = 0; e < NE; e++) acc[e] += bg[e];
        float m = acc[0];
#pragma unroll
        for (int e = 1; e < NE; e++) m = fmaxf(m, acc[e]);
        float s = 0.f, p[NE];
#pragma unroll
        for (int e = 0; e < NE; e++) { p[e] = __expf(acc[e] - m); s += p[e]; }
        float inv = 1.f / s;
        float* gp = &g_gate[(size_t)warp * NE];
        *(float4*)(gp)     = make_float4(p[0]*inv, p[1]*inv, p[2]*inv, p[3]*inv);
        *(float4*)(gp + 4) = make_float4(p[4]*inv, p[5]*inv, p[6]*inv, p[7]*inv);
    }
}

// ---------------------------------------------------------------------------
// Convert x -> fp16
// ---------------------------------------------------------------------------
__global__ __launch_bounds__(256) void conv_x_kernel(const float* __restrict__ x) {
    size_t i = ((size_t)blockIdx.x * blockDim.x + threadIdx.x) * 8;
    float4 a = *(const float4*)(x + i);
    float4 c = *(const float4*)(x + i + 4);
    float v[8] = {a.x, a.y, a.z, a.w, c.x, c.y, c.z, c.w};
    __align__(16) __half h[8];
#pragma unroll
    for (int j = 0; j < 8; j++) h[j] = __float2half_rn(v[j]);
    *(uint4*)&g_xh[i] = *(uint4*)h;
}

// ---------------------------------------------------------------------------
// Transpose + convert W: W[e,h,f] fp32 -> Wt[e,f,h] fp16
// ---------------------------------------------------------------------------
__global__ __launch_bounds__(256) void transpose_w(const float* __restrict__ W) {
    __shared__ float tile[32][33];
    const int e  = blockIdx.z;
    const int h0 = blockIdx.y * 32;
    const int f0 = blockIdx.x * 32;
    const int tx = threadIdx.x & 31;
    const int ty = threadIdx.x >> 5;
#pragma unroll
    for (int i = 0; i < 32; i += 8)
        tile[ty + i][tx] = W[((size_t)e * HID + h0 + ty + i) * HID + f0 + tx];
    __syncthreads();
#pragma unroll
    for (int i = 0; i < 32; i += 8) {
        float v = tile[tx][ty + i];
        g_wth[((size_t)e * HID + f0 + ty + i) * HID + h0 + tx] = __float2half_rn(v);
    }
}

// ---------------------------------------------------------------------------
// Main mma.sync kernel (fp16 in, fp32 accumulate).
// CTA: 128x128, 8 warps (2x4), warp tile 64x32, BK=32. NSLOT=4 ring,
// ONE barrier + ONE CP_WAIT per TWO stages. Prefetch pair p+1 into the
// slots the barrier proved drained (pair p-1's slots). 80B row stride.
// 2 CTAs/SM.
// ---------------------------------------------------------------------------
#define BK 32
#define ROWB 80
#define TILE_B (128 * ROWB)             // 10240
#define STAGE_B (2 * TILE_B)            // 20480
#define NSLOT 4
#define SMEM_MAIN (NSLOT * STAGE_B)     // 81920
#define TOT_ITERS (NE * (HID / BK))     // 512 (even; 256 pairs)

__global__ __launch_bounds__(256, 2)
void moe_mma_kernel(const float* __restrict__ bias,
                    const float* __restrict__ cached,
                    float* __restrict__ out) {
    extern __shared__ char sm[];
    const uint32_t sbase = smem_u32(sm);

    const int tid  = threadIdx.x;
    const int wid  = tid >> 5;
    const int lane = tid & 31;
    const int n0 = blockIdx.y * 128;
    const int f0 = blockIdx.x * 128;
    const int warp_m = wid >> 2;
    const int warp_n = wid & 3;

    // ---- global->smem load mapping: thread t -> row t>>1, 32B chunk (t&1)
    const int lr = tid >> 1;
    const int lc = (tid & 1) * 32;
    const __half* srcA = g_xh + (size_t)(n0 + lr) * HID + (lc >> 1);
    const size_t  bRow = (size_t)(f0 + lr) * HID + (lc >> 1);
    const uint32_t dstOff = (uint32_t)lr * ROWB + lc;

    // ---- ldmatrix offsets
    const uint32_t offA = (uint32_t)(warp_m * 64 + (lane & 15)) * ROWB
                        + (uint32_t)(lane >> 4) * 16;
    const int matb = lane >> 3;
    const uint32_t offB = (uint32_t)(warp_n * 32 + ((matb >> 1) * 8) + (lane & 7)) * ROWB
                        + (uint32_t)(matb & 1) * 16;

    float acc[4][4][4];
#pragma unroll
    for (int i = 0; i < 4; i++)
#pragma unroll
        for (int j = 0; j < 4; j++)
#pragma unroll
            for (int q = 0; q < 4; q++) acc[i][j][q] = 0.f;

    const uint32_t slotAddr[NSLOT] = { sbase, sbase + STAGE_B,
                                       sbase + 2 * STAGE_B, sbase + 3 * STAGE_B };

    auto load_stage = [&](int s, uint32_t slot) {
        const int e  = s >> 6;
        const int k0 = (s & 63) * BK;
        const uint32_t st = slot + dstOff;
        const __half* pa = srcA + k0;
        const __half* pb = g_wth + (size_t)e * HID * HID + bRow + k0;
        CP16(st,               pa);  CP16(st + 16,          pa + 8);
        CP16(st + TILE_B,      pb);  CP16(st + TILE_B + 16, pb + 8);
        CP_COMMIT();
    };

    auto compute_stage = [&](uint32_t stage) {
        uint32_t bh[16];
#pragma unroll
        for (int ks = 0; ks < 2; ks++) {
            LDSM_X4(bh[8*ks+0], bh[8*ks+1], bh[8*ks+2], bh[8*ks+3],
                    stage + TILE_B + offB + ks * 32);
            LDSM_X4(bh[8*ks+4], bh[8*ks+5], bh[8*ks+6], bh[8*ks+7],
                    stage + TILE_B + offB + 16 * ROWB + ks * 32);
        }
        uint32_t ah[2][4];
        LDSM_X4(ah[0][0], ah[0][1], ah[0][2], ah[0][3], stage + offA);
#pragma unroll
        for (int g = 0; g < 8; g++) {
            const int ks = g >> 2;
            const int mt = g & 3;
            const int cur = g & 1;
            if (g < 7) {
                const int gn = g + 1;
                LDSM_X4(ah[cur ^ 1][0], ah[cur ^ 1][1],
                        ah[cur ^ 1][2], ah[cur ^ 1][3],
                        stage + offA + (gn & 3) * (16 * ROWB) + (gn >> 2) * 32);
            }
#pragma unroll
            for (int nt = 0; nt < 4; nt++)
                mma16816(acc[mt][nt], ah[cur], &bh[8 * ks + 2 * nt]);
        }
    };

    // preload pair 0 (stages 0,1 -> slots 0,1)
    load_stage(0, slotAddr[0]);
    load_stage(1, slotAddr[1]);

    for (int p = 0; p < TOT_ITERS / 2; p++) {
        const int s0 = 2 * p;
        // only the current pair's 2 groups can be pending here
        CP_WAIT(0);
        __syncthreads();
        // prefetch pair p+1 into pair p-1's slots (drained per the barrier);
        // at p==0 those slots (2,3) were never used - also safe.
        if (s0 + 2 < TOT_ITERS) {
            load_stage(s0 + 2, slotAddr[(s0 + 2) & 3]);
            load_stage(s0 + 3, slotAddr[(s0 + 3) & 3]);
        }

        compute_stage(slotAddr[s0 & 3]);
        compute_stage(slotAddr[(s0 + 1) & 3]);

        // ---- epilogue at expert boundary (every 32 pairs)
        if ((p & 31) == 31) {
            const int e = p >> 5;
#pragma unroll
            for (int nt = 0; nt < 4; nt++) {
                const int col = f0 + warp_n * 32 + nt * 8 + (lane & 3) * 2;
                const float2 bb = *(const float2*)&bias[(size_t)e * HID + col];
                const float2 cc = *(const float2*)&cached[(size_t)e * HID + col];
#pragma unroll
                for (int mt = 0; mt < 4; mt++) {
                    const int row0 = n0 + warp_m * 64 + mt * 16 + (lane >> 2);
                    const float g0 = g_gate[(size_t)row0 * NE + e];
                    const float g1 = g_gate[(size_t)(row0 + 8) * NE + e];
                    float* p0 = out + (size_t)row0 * HID + col;
                    float* p1 = out + (size_t)(row0 + 8) * HID + col;
                    float2 v0, v1;
                    v0.x = g0 * (fmaxf(acc[mt][nt][0] + bb.x, 0.f) + cc.x);
                    v0.y = g0 * (fmaxf(acc[mt][nt][1] + bb.y, 0.f) + cc.y);
                    v1.x = g1 * (fmaxf(acc[mt][nt][2] + bb.x, 0.f) + cc.x);
                    v1.y = g1 * (fmaxf(acc[mt][nt][3] + bb.y, 0.f) + cc.y);
                    if (e == 0) {
                        *(float2*)p0 = v0;
                        *(float2*)p1 = v1;
                    } else {
                        float2 o0 = *(const float2*)p0;
                        float2 o1 = *(const float2*)p1;
                        o0.x += v0.x; o0.y += v0.y;
                        o1.x += v1.x; o1.y += v1.y;
                        *(float2*)p0 = o0;
                        *(float2*)p1 = o1;
                    }
                    acc[mt][nt][0] = 0.f; acc[mt][nt][1] = 0.f;
                    acc[mt][nt][2] = 0.f; acc[mt][nt][3] = 0.f;
                }
            }
        }
    }
}

// ---------------------------------------------------------------------------
// Launch
// inputs: x[8192*2048], W[8*2048*2048], b[8*2048], Wg[2048*8], bg[8], cached[8*2048]
// ---------------------------------------------------------------------------
extern "C" void kernel_launch(void* const* d_in, const int* in_sizes, int n_in,
                              void* d_out, int out_size) {
    const float* x      = (const float*)d_in[0];
    const float* W      = (const float*)d_in[1];
    const float* b      = (const float*)d_in[2];
    const float* Wg     = (const float*)d_in[3];
    const float* bg     = (const float*)d_in[4];
    const float* cached = (const float*)d_in[5];
    float* out = (float*)d_out;

    gate_kernel<<<N_TOK / 8, 256>>>(x, Wg, bg);
    conv_x_kernel<<<(N_TOK * HID) / (256 * 8), 256>>>(x);
    transpose_w<<<dim3(HID / 32, HID / 32, NE), 256>>>(W);

    static bool attr_set = false;
    if (!attr_set) {
        cudaFuncSetAttribute(moe_mma_kernel,
                             cudaFuncAttributeMaxDynamicSharedMemorySize, SMEM_MAIN);
        attr_set = true;
    }
    moe_mma_kernel<<<dim3(HID / 128, N_TOK / 128), 256, SMEM_MAIN>>>(b, cached, out);
}

// round 15
// speedup vs baseline: 1.4459x; 1.0494x over previous
#include <cuda_runtime.h>
#include <cuda_fp16.h>
#include <cstdint>

#define N_TOK 8192
#define HID   2048
#define NE    8

// ---------------------------------------------------------------------------
// Static device scratch
// ---------------------------------------------------------------------------
__device__ float  g_gate[N_TOK * NE];
__device__ __half g_xh [(size_t)N_TOK * HID];              // x in fp16
__device__ __half g_wth[(size_t)NE * HID * HID];           // W^T fp16 [e][f][h]

// ---------------------------------------------------------------------------
// PTX helpers (baseline sm_80/75-era only)
// ---------------------------------------------------------------------------
__device__ __forceinline__ uint32_t smem_u32(const void* p) {
    uint32_t a;
    asm("{ .reg .u64 t; cvta.to.shared.u64 t, %1; cvt.u32.u64 %0, t; }"
        : "=r"(a) : "l"(p));
    return a;
}
#define CP16(dst, src) \
    asm volatile("cp.async.cg.shared.global [%0], [%1], 16;" \
                 :: "r"(dst), "l"(src) : "memory")
#define CP_COMMIT() asm volatile("cp.async.commit_group;" ::: "memory")
#define CP_WAIT(n)  asm volatile("cp.async.wait_group %0;" :: "n"(n) : "memory")

#define LDSM_X4(r0, r1, r2, r3, a) \
    asm volatile("ldmatrix.sync.aligned.m8n8.x4.shared.b16 {%0,%1,%2,%3}, [%4];" \
                 : "=r"(r0), "=r"(r1), "=r"(r2), "=r"(r3) : "r"(a))

__device__ __forceinline__ void mma16816(float* d, const uint32_t* a,
                                         const uint32_t* bfr) {
    asm volatile(
        "mma.sync.aligned.m16n8k16.row.col.f32.f16.f16.f32 "
        "{%0,%1,%2,%3}, {%4,%5,%6,%7}, {%8,%9}, {%0,%1,%2,%3};"
        : "+f"(d[0]), "+f"(d[1]), "+f"(d[2]), "+f"(d[3])
        : "r"(a[0]), "r"(a[1]), "r"(a[2]), "r"(a[3]), "r"(bfr[0]), "r"(bfr[1]));
}

// ---------------------------------------------------------------------------
// Gate + x->fp16 kernel. 512 threads = 16 warps = 16 tokens per block.
// Wg^T staged in 64KB smem (conflict-free float4 reads); x read once,
// fp16 copy stored coalesced (replaces the separate conv_x kernel).
// ---------------------------------------------------------------------------
__global__ __launch_bounds__(512)
void gate_conv_kernel(const float* __restrict__ x,
                      const float* __restrict__ Wg,
                      const float* __restrict__ bg) {
    extern __shared__ float Wgs[];       // [NE][HID] = 64KB
    const int tid  = threadIdx.x;
    const int wid  = tid >> 5;
    const int lane = tid & 31;

    // stage Wg^T: Wg is [HID][NE] row-major; Wgs[e][h]
#pragma unroll
    for (int j = 0; j < (HID * NE) / 512; j++) {
        int idx = tid + j * 512;
        int h = idx >> 3, e = idx & 7;
        Wgs[e * HID + h] = Wg[idx];
    }
    __syncthreads();

    const int token = blockIdx.x * 16 + wid;
    const float* xr = x + (size_t)token * HID;
    __half* xo = g_xh + (size_t)token * HID;

    float acc[NE];
#pragma unroll
    for (int e = 0; e < NE; e++) acc[e] = 0.f;

#pragma unroll 4
    for (int k0 = lane * 4; k0 < HID; k0 += 128) {
        float4 xv = *(const float4*)(xr + k0);
        // fused fp16 conversion (coalesced 8B store per lane)
        __align__(8) __half hx[4] = {
            __float2half_rn(xv.x), __float2half_rn(xv.y),
            __float2half_rn(xv.z), __float2half_rn(xv.w) };
        *(uint2*)(xo + k0) = *(uint2*)hx;
#pragma unroll
        for (int e = 0; e < NE; e++) {
            float4 w = *(const float4*)&Wgs[e * HID + k0];
            acc[e] += xv.x * w.x + xv.y * w.y + xv.z * w.z + xv.w * w.w;
        }
    }
#pragma unroll
    for (int e = 0; e < NE; e++)
#pragma unroll
        for (int o = 16; o; o >>= 1)
            acc[e] += __shfl_xor_sync(0xFFFFFFFFu, acc[e], o);
    if (lane == 0) {
#pragma unroll
        for (int e = 0; e < NE; e++) acc[e] += bg[e];
        float m = acc[0];
#pragma unroll
        for (int e = 1; e < NE; e++) m = fmaxf(m, acc[e]);
        float s = 0.f, p[NE];
#pragma unroll
        for (int e = 0; e < NE; e++) { p[e] = __expf(acc[e] - m); s += p[e]; }
        float inv = 1.f / s;
        float* gp = &g_gate[(size_t)token * NE];
        *(float4*)(gp)     = make_float4(p[0]*inv, p[1]*inv, p[2]*inv, p[3]*inv);
        *(float4*)(gp + 4) = make_float4(p[4]*inv, p[5]*inv, p[6]*inv, p[7]*inv);
    }
}

// ---------------------------------------------------------------------------
// Transpose + convert W: W[e,h,f] fp32 -> Wt[e,f,h] fp16.
// 64(h) x 32(f) tiles; store phase emits 16B uint4 (8 halfs) with c-fastest
// lane order -> 128B contiguous global store segments.
// ---------------------------------------------------------------------------
__global__ __launch_bounds__(256) void transpose_w(const float* __restrict__ W) {
    __shared__ float tile[64][33];
    const int e  = blockIdx.z;
    const int h0 = blockIdx.y * 64;
    const int f0 = blockIdx.x * 32;

    const int tid = threadIdx.x;
    // load: 64 rows x 32 cols, 2 float4 per thread, coalesced
#pragma unroll
    for (int j = 0; j < 2; j++) {
        int idx4 = tid + j * 256;          // 0..511 float4s
        int h  = idx4 >> 3;                // 0..63
        int f4 = idx4 & 7;                 // 0..7
        float4 v = *(const float4*)&W[((size_t)e * HID + h0 + h) * HID + f0 + f4 * 4];
        tile[h][f4 * 4 + 0] = v.x;
        tile[h][f4 * 4 + 1] = v.y;
        tile[h][f4 * 4 + 2] = v.z;
        tile[h][f4 * 4 + 3] = v.w;
    }
    __syncthreads();

    // store: thread -> f-row r (0..31), h-chunk c (0..7) of 8 halfs (16B)
    const int r = tid >> 3;
    const int c = tid & 7;
    __align__(16) __half hv[8];
#pragma unroll
    for (int q = 0; q < 8; q++)
        hv[q] = __float2half_rn(tile[8 * c + q][r]);
    *(uint4*)&g_wth[((size_t)e * HID + f0 + r) * HID + h0 + 8 * c] = *(uint4*)hv;
}

// ---------------------------------------------------------------------------
// Main mma.sync kernel (fp16 in, fp32 accumulate) — proven R8 structure.
// CTA: 128x128, 8 warps (2x4), warp tile 64x32, BK=32, NSLOT=3 ring,
// single barrier/stage, frag pipelining. 80B row stride. 2 CTAs/SM.
// ---------------------------------------------------------------------------
#define BK 32
#define ROWB 80
#define TILE_B (128 * ROWB)             // 10240
#define STAGE_B (2 * TILE_B)            // 20480
#define NSLOT 3
#define SMEM_MAIN (NSLOT * STAGE_B)     // 61440
#define TOT_ITERS (NE * (HID / BK))     // 512

__global__ __launch_bounds__(256, 2)
void moe_mma_kernel(const float* __restrict__ bias,
                    const float* __restrict__ cached,
                    float* __restrict__ out) {
    extern __shared__ char sm[];
    const uint32_t sbase = smem_u32(sm);

    const int tid  = threadIdx.x;
    const int wid  = tid >> 5;
    const int lane = tid & 31;
    const int n0 = blockIdx.y * 128;
    const int f0 = blockIdx.x * 128;
    const int warp_m = wid >> 2;
    const int warp_n = wid & 3;

    const int lr = tid >> 1;
    const int lc = (tid & 1) * 32;
    const __half* srcA = g_xh + (size_t)(n0 + lr) * HID + (lc >> 1);
    const size_t  bRow = (size_t)(f0 + lr) * HID + (lc >> 1);
    const uint32_t dstOff = (uint32_t)lr * ROWB + lc;

    const uint32_t offA = (uint32_t)(warp_m * 64 + (lane & 15)) * ROWB
                        + (uint32_t)(lane >> 4) * 16;
    const int matb = lane >> 3;
    const uint32_t offB = (uint32_t)(warp_n * 32 + ((matb >> 1) * 8) + (lane & 7)) * ROWB
                        + (uint32_t)(matb & 1) * 16;

    float acc[4][4][4];
#pragma unroll
    for (int i = 0; i < 4; i++)
#pragma unroll
        for (int j = 0; j < 4; j++)
#pragma unroll
            for (int q = 0; q < 4; q++) acc[i][j][q] = 0.f;

    const uint32_t slotAddr[NSLOT] = { sbase, sbase + STAGE_B, sbase + 2 * STAGE_B };

    auto load_stage = [&](int s, uint32_t slot) {
        const int e  = s >> 6;
        const int k0 = (s & 63) * BK;
        const uint32_t st = slot + dstOff;
        const __half* pa = srcA + k0;
        const __half* pb = g_wth + (size_t)e * HID * HID + bRow + k0;
        CP16(st,               pa);  CP16(st + 16,          pa + 8);
        CP16(st + TILE_B,      pb);  CP16(st + TILE_B + 16, pb + 8);
        CP_COMMIT();
    };

    load_stage(0, slotAddr[0]);
    load_stage(1, slotAddr[1]);
    int wslot = 2, rslot = 0;

    for (int s = 0; s < TOT_ITERS; s++) {
        if (s + 1 < TOT_ITERS) { CP_WAIT(1); }
        else                   { CP_WAIT(0); }
        __syncthreads();
        if (s + 2 < TOT_ITERS) {
            load_stage(s + 2, slotAddr[wslot]);
            if (++wslot == NSLOT) wslot = 0;
        }
        const uint32_t stage = slotAddr[rslot];
        if (++rslot == NSLOT) rslot = 0;

        uint32_t bh[16];
#pragma unroll
        for (int ks = 0; ks < 2; ks++) {
            LDSM_X4(bh[8*ks+0], bh[8*ks+1], bh[8*ks+2], bh[8*ks+3],
                    stage + TILE_B + offB + ks * 32);
            LDSM_X4(bh[8*ks+4], bh[8*ks+5], bh[8*ks+6], bh[8*ks+7],
                    stage + TILE_B + offB + 16 * ROWB + ks * 32);
        }
        uint32_t ah[2][4];
        LDSM_X4(ah[0][0], ah[0][1], ah[0][2], ah[0][3], stage + offA);
#pragma unroll
        for (int g = 0; g < 8; g++) {
            const int ks = g >> 2;
            const int mt = g & 3;
            const int cur = g & 1;
            if (g < 7) {
                const int gn = g + 1;
                LDSM_X4(ah[cur ^ 1][0], ah[cur ^ 1][1],
                        ah[cur ^ 1][2], ah[cur ^ 1][3],
                        stage + offA + (gn & 3) * (16 * ROWB) + (gn >> 2) * 32);
            }
#pragma unroll
            for (int nt = 0; nt < 4; nt++)
                mma16816(acc[mt][nt], ah[cur], &bh[8 * ks + 2 * nt]);
        }

        if ((s & 63) == 63) {
            const int e = s >> 6;
#pragma unroll
            for (int nt = 0; nt < 4; nt++) {
                const int col = f0 + warp_n * 32 + nt * 8 + (lane & 3) * 2;
                const float2 bb = *(const float2*)&bias[(size_t)e * HID + col];
                const float2 cc = *(const float2*)&cached[(size_t)e * HID + col];
#pragma unroll
                for (int mt = 0; mt < 4; mt++) {
                    const int row0 = n0 + warp_m * 64 + mt * 16 + (lane >> 2);
                    const float g0 = g_gate[(size_t)row0 * NE + e];
                    const float g1 = g_gate[(size_t)(row0 + 8) * NE + e];
                    float* p0 = out + (size_t)row0 * HID + col;
                    float* p1 = out + (size_t)(row0 + 8) * HID + col;
                    float2 v0, v1;
                    v0.x = g0 * (fmaxf(acc[mt][nt][0] + bb.x, 0.f) + cc.x);
                    v0.y = g0 * (fmaxf(acc[mt][nt][1] + bb.y, 0.f) + cc.y);
                    v1.x = g1 * (fmaxf(acc[mt][nt][2] + bb.x, 0.f) + cc.x);
                    v1.y = g1 * (fmaxf(acc[mt][nt][3] + bb.y, 0.f) + cc.y);
                    if (e == 0) {
                        *(float2*)p0 = v0;
                        *(float2*)p1 = v1;
                    } else {
                        float2 o0 = *(const float2*)p0;
                        float2 o1 = *(const float2*)p1;
                        o0.x += v0.x; o0.y += v0.y;
                        o1.x += v1.x; o1.y += v1.y;
                        *(float2*)p0 = o0;
                        *(float2*)p1 = o1;
                    }
                    acc[mt][nt][0] = 0.f; acc[mt][nt][1] = 0.f;
                    acc[mt][nt][2] = 0.f; acc[mt][nt][3] = 0.f;
                }
            }
        }
    }
}

// ---------------------------------------------------------------------------
// Launch
// inputs: x[8192*2048], W[8*2048*2048], b[8*2048], Wg[2048*8], bg[8], cached[8*2048]
// ---------------------------------------------------------------------------
extern "C" void kernel_launch(void* const* d_in, const int* in_sizes, int n_in,
                              void* d_out, int out_size) {
    const float* x      = (const float*)d_in[0];
    const float* W      = (const float*)d_in[1];
    const float* b      = (const float*)d_in[2];
    const float* Wg     = (const float*)d_in[3];
    const float* bg     = (const float*)d_in[4];
    const float* cached = (const float*)d_in[5];
    float* out = (float*)d_out;

    static bool attr_set = false;
    if (!attr_set) {
        cudaFuncSetAttribute(gate_conv_kernel,
                             cudaFuncAttributeMaxDynamicSharedMemorySize,
                             NE * HID * (int)sizeof(float));
        cudaFuncSetAttribute(moe_mma_kernel,
                             cudaFuncAttributeMaxDynamicSharedMemorySize, SMEM_MAIN);
        attr_set = true;
    }

    gate_conv_kernel<<<N_TOK / 16, 512, NE * HID * sizeof(float)>>>(x, Wg, bg);
    transpose_w<<<dim3(HID / 32, HID / 64, NE), 256>>>(W);
    moe_mma_kernel<<<dim3(HID / 128, N_TOK / 128), 256, SMEM_MAIN>>>(b, cached, out);
}